// round 6
// baseline (speedup 1.0000x reference)
#include <cuda_runtime.h>

#define NNODES 100000
#define NEDGES 1600000
#define NB1 ((NNODES + 255) / 256)   // 391 scan blocks

typedef unsigned long long ull;

// ---------------- scratch (device globals: allocation-free) ----------------
// ONLY referenced from device code (host-side &global is a shadow symbol).
__device__ int   g_is64;
__device__ float g_deg[NNODES];
__device__ float g_dis[NNODES];
__device__ int   g_hist[NNODES];
__device__ int   g_row[NNODES + 1];
__device__ int   g_cursor[NNODES];
__device__ int   g_bsums[NB1];
__device__ int2  g_edge[NEDGES];              // {src, norm-bits}, dst-sorted
__device__ float g_h1[(size_t)NNODES * 128];
__device__ float g_a1[(size_t)NNODES * 128];
__device__ float g_h2[(size_t)NNODES * 64];

// ---------------- f32x2 packed-math helpers ----------------
__device__ __forceinline__ ull dup2(float v) {
    ull r;
    asm("mov.b64 %0, {%1,%1};" : "=l"(r) : "r"(__float_as_uint(v)));
    return r;
}
__device__ __forceinline__ ull fma2(ull a, ull b, ull c) {
    ull d;
    asm("fma.rn.f32x2 %0, %1, %2, %3;" : "=l"(d) : "l"(a), "l"(b), "l"(c));
    return d;
}
__device__ __forceinline__ float lo32(ull v) { return __uint_as_float((unsigned)v); }
__device__ __forceinline__ float hi32(ull v) { return __uint_as_float((unsigned)(v >> 32)); }

// ---------------- init (+ fused edge_index dtype detection) ----------------
__global__ void k_init(const int* __restrict__ ei_raw) {
    int i = blockIdx.x * 256 + threadIdx.x;
    if (i < NNODES) { g_deg[i] = 1.0f; g_hist[i] = 0; }   // self-loop weight 1
    if (blockIdx.x == 0) {
        int bad = 0;
        for (int k = threadIdx.x; k < 2048; k += 256)
            bad |= (ei_raw[2 * k + 1] != 0);   // int64 high words all zero
        bad = __syncthreads_or(bad);
        if (threadIdx.x == 0) g_is64 = !bad;
    }
}

__device__ __forceinline__ void load_edge(const void* __restrict__ ei, int e,
                                          int& s, int& d) {
    if (g_is64) {
        const long long* p = (const long long*)ei;
        s = (int)p[e];
        d = (int)p[NEDGES + e];
    } else {
        const int* p = (const int*)ei;
        s = p[e];
        d = p[NEDGES + e];
    }
}

__global__ void k_deg(const void* __restrict__ ei, const float* __restrict__ ew) {
    int e = blockIdx.x * 256 + threadIdx.x;
    if (e < NEDGES) {
        int s, d;
        load_edge(ei, e, s, d);
        atomicAdd(&g_deg[d], ew[e]);
        atomicAdd(&g_hist[d], 1);
    }
}

// ---------------- scan (hist -> row_ptr), fused dis ----------------
__global__ void k_scan1() {
    __shared__ int sh[256];
    int i = blockIdx.x * 256 + threadIdx.x;
    int tid = threadIdx.x;
    if (i < NNODES) g_dis[i] = rsqrtf(g_deg[i]);     // deg >= 1 always
    int v = (i < NNODES) ? g_hist[i] : 0;
    sh[tid] = v; __syncthreads();
    for (int off = 1; off < 256; off <<= 1) {
        int t = (tid >= off) ? sh[tid - off] : 0;
        __syncthreads(); sh[tid] += t; __syncthreads();
    }
    if (i < NNODES) g_row[i] = sh[tid] - v;
    if (tid == 255) g_bsums[blockIdx.x] = sh[tid];
}

__global__ void k_scan2() {   // single block, 512 >= NB1
    __shared__ int sh[512];
    int tid = threadIdx.x;
    int v = (tid < NB1) ? g_bsums[tid] : 0;
    sh[tid] = v; __syncthreads();
    for (int off = 1; off < 512; off <<= 1) {
        int t = (tid >= off) ? sh[tid - off] : 0;
        __syncthreads(); sh[tid] += t; __syncthreads();
    }
    if (tid < NB1) g_bsums[tid] = sh[tid] - v;
}

__global__ void k_scan3() {
    int i = blockIdx.x * 256 + threadIdx.x;
    if (i < NNODES) {
        int r = g_row[i] + g_bsums[blockIdx.x];
        g_row[i] = r;
        g_cursor[i] = r;
        if (i == 0) g_row[NNODES] = NEDGES;
    }
}

__global__ void k_sort(const void* __restrict__ ei, const float* __restrict__ ew) {
    int e = blockIdx.x * 256 + threadIdx.x;
    if (e < NEDGES) {
        int s, d;
        load_edge(ei, e, s, d);
        float nrm = g_dis[s] * ew[e] * g_dis[d];
        int pos = atomicAdd(&g_cursor[d], 1);
        g_edge[pos] = make_int2(s, __float_as_int(nrm));
    }
}

// ---------------- GEMM via packed f32x2: (M x 128) @ (128 x NCOL) ----------
// X values duplicated into u64 smem at tile-load time; B read as natural
// column-pairs. Inner loop: 6 LDS.128 + 32 FMA2 per kk, zero movs.
template<int NCOL, int LAYER>
__global__ __launch_bounds__(256, 2) void gemm(
    const float* __restrict__ Xin, const float* __restrict__ W, int M)
{
    constexpr int TC = NCOL / 16;    // cols per thread (8 or 4)
    constexpr int CP = TC / 2;       // col-pairs per thread (4 or 2)
    constexpr int BK = 32;
    constexpr int XR = 132;          // u64 stride (even -> 16B-aligned rows)

    extern __shared__ __align__(16) char smem[];
    ull*   Xs = reinterpret_cast<ull*>(smem);                  // [BK][XR] dup'd X
    float* Ws = reinterpret_cast<float*>(smem + BK * XR * 8);  // [BK][NCOL]

    const float* __restrict__ X = (LAYER == 1) ? Xin : g_a1;
    float* __restrict__ H = (LAYER == 1) ? g_h1 : g_h2;

    const int tid  = threadIdx.x;
    const int row0 = blockIdx.x * 128;
    const int tc   = tid & 15;
    const int tr   = tid >> 4;

    ull acc[8][CP];
#pragma unroll
    for (int i = 0; i < 8; i++)
#pragma unroll
        for (int j = 0; j < CP; j++) acc[i][j] = 0ull;

    for (int kt = 0; kt < 128 / BK; kt++) {
        // X tile: transpose to k-major AND duplicate each value into u64
#pragma unroll
        for (int idx = tid; idx < 128 * BK / 4; idx += 256) {
            int r = idx >> 3, c4 = idx & 7;
            float4 v = make_float4(0.f, 0.f, 0.f, 0.f);
            int gr = row0 + r;
            if (gr < M)
                v = reinterpret_cast<const float4*>(X)[(size_t)gr * 32 + kt * 8 + c4];
            int kk = c4 * 4;
            Xs[(kk + 0) * XR + r] = dup2(v.x);
            Xs[(kk + 1) * XR + r] = dup2(v.y);
            Xs[(kk + 2) * XR + r] = dup2(v.z);
            Xs[(kk + 3) * XR + r] = dup2(v.w);
        }
        // W tile (rows kt*BK .. +BK, contiguous)
#pragma unroll
        for (int idx = tid; idx < BK * NCOL / 4; idx += 256)
            reinterpret_cast<float4*>(Ws)[idx] =
                reinterpret_cast<const float4*>(W)[kt * (BK * NCOL / 4) + idx];
        __syncthreads();

#pragma unroll
        for (int kk = 0; kk < BK; kk++) {
            // 8 duplicated row-values: 4 x LDS.128
            ull a[8];
#pragma unroll
            for (int i = 0; i < 4; i++) {
                ulonglong2 t = *reinterpret_cast<const ulonglong2*>(
                    &Xs[kk * XR + tr * 8 + 2 * i]);
                a[2 * i] = t.x; a[2 * i + 1] = t.y;
            }
            // CP natural column-pairs: CP/2 x LDS.128
            ull b[CP];
#pragma unroll
            for (int g = 0; g < CP / 2; g++) {
                ulonglong2 u = *reinterpret_cast<const ulonglong2*>(
                    &Ws[kk * NCOL + tc * TC + 4 * g]);
                b[2 * g] = u.x; b[2 * g + 1] = u.y;
            }
#pragma unroll
            for (int i = 0; i < 8; i++)
#pragma unroll
                for (int j = 0; j < CP; j++)
                    acc[i][j] = fma2(a[i], b[j], acc[i][j]);
        }
        __syncthreads();
    }

    // epilogue: acc[i][j] holds cols (tc*TC+2j, +1) of row row0+tr*8+i
#pragma unroll
    for (int i = 0; i < 8; i++) {
        int r = row0 + tr * 8 + i;
        if (r >= M) continue;
#pragma unroll
        for (int g = 0; g < CP / 2; g++) {
            float4 v = make_float4(lo32(acc[i][2 * g]),     hi32(acc[i][2 * g]),
                                   lo32(acc[i][2 * g + 1]), hi32(acc[i][2 * g + 1]));
            reinterpret_cast<float4*>(H)[((size_t)r * NCOL + tc * TC + 4 * g) >> 2] = v;
        }
    }
}

// ---------------- segmented aggregation: one warp per dst node --------------
// a1[d] = relu( b1 + dis[d]^2*h1[d] + sum_e norm_e * h1[src_e] ),  C=128
__global__ __launch_bounds__(256) void agg1(const float* __restrict__ bias) {
    int w = (blockIdx.x * 256 + threadIdx.x) >> 5;
    int lane = threadIdx.x & 31;
    if (w >= NNODES) return;
    const ulonglong2* H = reinterpret_cast<const ulonglong2*>(g_h1);

    int beg = g_row[w], end = g_row[w + 1];
    float ds = g_dis[w];
    ull s2 = dup2(ds * ds);
    ulonglong2 hself = H[(size_t)w * 32 + lane];
    ull acc0 = fma2(s2, hself.x, 0ull);
    ull acc1 = fma2(s2, hself.y, 0ull);
    ull acc2 = 0ull, acc3 = 0ull;

    int e = beg;
    for (; e + 1 < end; e += 2) {
        int2 md0 = g_edge[e];
        int2 md1 = g_edge[e + 1];
        ull nm0 = dup2(__int_as_float(md0.y));
        ull nm1 = dup2(__int_as_float(md1.y));
        ulonglong2 h0 = H[(size_t)md0.x * 32 + lane];
        ulonglong2 h1 = H[(size_t)md1.x * 32 + lane];
        acc0 = fma2(nm0, h0.x, acc0);
        acc1 = fma2(nm0, h0.y, acc1);
        acc2 = fma2(nm1, h1.x, acc2);
        acc3 = fma2(nm1, h1.y, acc3);
    }
    if (e < end) {
        int2 md = g_edge[e];
        ull nm = dup2(__int_as_float(md.y));
        ulonglong2 hv = H[(size_t)md.x * 32 + lane];
        acc0 = fma2(nm, hv.x, acc0);
        acc1 = fma2(nm, hv.y, acc1);
    }
    float4 bv = reinterpret_cast<const float4*>(bias)[lane];
    float4 o;
    o.x = fmaxf(lo32(acc0) + lo32(acc2) + bv.x, 0.f);
    o.y = fmaxf(hi32(acc0) + hi32(acc2) + bv.y, 0.f);
    o.z = fmaxf(lo32(acc1) + lo32(acc3) + bv.z, 0.f);
    o.w = fmaxf(hi32(acc1) + hi32(acc3) + bv.w, 0.f);
    reinterpret_cast<float4*>(g_a1)[(size_t)w * 32 + lane] = o;
}

// out[d] = b2 + dis[d]^2*h2[d] + sum_e norm_e * h2[src_e],  C=64
__global__ __launch_bounds__(256) void agg2(const float* __restrict__ bias,
                                            float* __restrict__ out) {
    int w = (blockIdx.x * 256 + threadIdx.x) >> 5;
    int lane = threadIdx.x & 31;
    if (w >= NNODES) return;
    const ull* H = reinterpret_cast<const ull*>(g_h2);   // 32 u64 per row

    int beg = g_row[w], end = g_row[w + 1];
    float ds = g_dis[w];
    ull s2 = dup2(ds * ds);
    ull acc0 = fma2(s2, H[(size_t)w * 32 + lane], 0ull);
    ull acc1 = 0ull;

    int e = beg;
    for (; e + 1 < end; e += 2) {
        int2 md0 = g_edge[e];
        int2 md1 = g_edge[e + 1];
        ull nm0 = dup2(__int_as_float(md0.y));
        ull nm1 = dup2(__int_as_float(md1.y));
        acc0 = fma2(nm0, H[(size_t)md0.x * 32 + lane], acc0);
        acc1 = fma2(nm1, H[(size_t)md1.x * 32 + lane], acc1);
    }
    if (e < end) {
        int2 md = g_edge[e];
        ull nm = dup2(__int_as_float(md.y));
        acc0 = fma2(nm, H[(size_t)md.x * 32 + lane], acc0);
    }
    float2 bv = reinterpret_cast<const float2*>(bias)[lane];
    float2 o;
    o.x = lo32(acc0) + lo32(acc1) + bv.x;
    o.y = hi32(acc0) + hi32(acc1) + bv.y;
    reinterpret_cast<float2*>(out)[(size_t)w * 32 + lane] = o;
}

// ---------------- launch ----------------
extern "C" void kernel_launch(void* const* d_in, const int* in_sizes, int n_in,
                              void* d_out, int out_size)
{
    const float* x  = (const float*)d_in[0];
    const void*  ei = d_in[1];
    const float* ew = (const float*)d_in[2];
    const float* W1 = (const float*)d_in[3];
    const float* b1 = (const float*)d_in[4];
    const float* W2 = (const float*)d_in[5];
    const float* b2 = (const float*)d_in[6];
    float* out = (float*)d_out;

    const int nb_nodes = (NNODES + 255) / 256;
    const int nb_edges = (NEDGES + 255) / 256;
    const int nb_rows  = (NNODES + 127) / 128;
    const int nb_warps = (NNODES * 32 + 255) / 256;

    constexpr int SM1 = 32 * 132 * 8 + 32 * 128 * 4;   // 50176 B
    constexpr int SM2 = 32 * 132 * 8 + 32 * 64 * 4;    // 41984 B
    cudaFuncSetAttribute(gemm<128, 1>, cudaFuncAttributeMaxDynamicSharedMemorySize, SM1);
    cudaFuncSetAttribute(gemm<64, 2>,  cudaFuncAttributeMaxDynamicSharedMemorySize, SM2);

    // order chosen so ncu -s 5 lands on gemm<128,1>
    k_init<<<nb_nodes, 256>>>((const int*)ei);          // 0
    k_deg<<<nb_edges, 256>>>(ei, ew);                   // 1
    k_scan1<<<nb_nodes, 256>>>();                       // 2
    k_scan2<<<1, 512>>>();                              // 3
    k_scan3<<<nb_nodes, 256>>>();                       // 4
    gemm<128, 1><<<nb_rows, 256, SM1>>>(x, W1, NNODES); // 5  <- profiled
    k_sort<<<nb_edges, 256>>>(ei, ew);                  // 6
    agg1<<<nb_warps, 256>>>(b1);                        // 7
    gemm<64, 2><<<nb_rows, 256, SM2>>>(nullptr, W2, NNODES); // 8
    agg2<<<nb_warps, 256>>>(b2, out);                   // 9
}

// round 7
// speedup vs baseline: 1.1982x; 1.1982x over previous
#include <cuda_runtime.h>

#define NNODES 100000
#define NEDGES 1600000
#define NB1 ((NNODES + 255) / 256)   // 391 scan blocks

typedef unsigned long long ull;

// ---------------- scratch (device globals: allocation-free) ----------------
// ONLY referenced from device code (host-side &global is a shadow symbol).
__device__ int   g_is64;
__device__ float g_deg[NNODES];
__device__ float g_dis[NNODES];
__device__ int   g_hist[NNODES];
__device__ int   g_row[NNODES + 1];
__device__ int   g_cursor[NNODES];
__device__ int   g_bsums[NB1];
__device__ int2  g_edge[NEDGES];              // {src, norm-bits}, dst-sorted
__device__ float g_h1[(size_t)NNODES * 128];
__device__ float g_a1[(size_t)NNODES * 128];
__device__ float g_h2[(size_t)NNODES * 64];

// ---------------- f32x2 packed-math helpers ----------------
__device__ __forceinline__ ull dup2(float v) {
    ull r;
    asm("mov.b64 %0, {%1,%1};" : "=l"(r) : "r"(__float_as_uint(v)));
    return r;
}
__device__ __forceinline__ ull fma2(ull a, ull b, ull c) {
    ull d;
    asm("fma.rn.f32x2 %0, %1, %2, %3;" : "=l"(d) : "l"(a), "l"(b), "l"(c));
    return d;
}
__device__ __forceinline__ float lo32(ull v) { return __uint_as_float((unsigned)v); }
__device__ __forceinline__ float hi32(ull v) { return __uint_as_float((unsigned)(v >> 32)); }

// ---------------- init (+ fused edge_index dtype detection) ----------------
__global__ void k_init(const int* __restrict__ ei_raw) {
    int i = blockIdx.x * 256 + threadIdx.x;
    if (i < NNODES) { g_deg[i] = 1.0f; g_hist[i] = 0; }   // self-loop weight 1
    if (blockIdx.x == 0) {
        int bad = 0;
        for (int k = threadIdx.x; k < 2048; k += 256)
            bad |= (ei_raw[2 * k + 1] != 0);   // int64 high words all zero
        bad = __syncthreads_or(bad);
        if (threadIdx.x == 0) g_is64 = !bad;
    }
}

__device__ __forceinline__ void load_edge(const void* __restrict__ ei, int e,
                                          int& s, int& d) {
    if (g_is64) {
        const long long* p = (const long long*)ei;
        s = (int)p[e];
        d = (int)p[NEDGES + e];
    } else {
        const int* p = (const int*)ei;
        s = p[e];
        d = p[NEDGES + e];
    }
}

__global__ void k_deg(const void* __restrict__ ei, const float* __restrict__ ew) {
    int e = blockIdx.x * 256 + threadIdx.x;
    if (e < NEDGES) {
        int s, d;
        load_edge(ei, e, s, d);
        atomicAdd(&g_deg[d], ew[e]);
        atomicAdd(&g_hist[d], 1);
    }
}

// ---------------- scan (hist -> row_ptr), fused dis ----------------
__global__ void k_scan1() {
    __shared__ int sh[256];
    int i = blockIdx.x * 256 + threadIdx.x;
    int tid = threadIdx.x;
    if (i < NNODES) g_dis[i] = rsqrtf(g_deg[i]);     // deg >= 1 always
    int v = (i < NNODES) ? g_hist[i] : 0;
    sh[tid] = v; __syncthreads();
    for (int off = 1; off < 256; off <<= 1) {
        int t = (tid >= off) ? sh[tid - off] : 0;
        __syncthreads(); sh[tid] += t; __syncthreads();
    }
    if (i < NNODES) g_row[i] = sh[tid] - v;
    if (tid == 255) g_bsums[blockIdx.x] = sh[tid];
}

__global__ void k_scan2() {   // single block, 512 >= NB1
    __shared__ int sh[512];
    int tid = threadIdx.x;
    int v = (tid < NB1) ? g_bsums[tid] : 0;
    sh[tid] = v; __syncthreads();
    for (int off = 1; off < 512; off <<= 1) {
        int t = (tid >= off) ? sh[tid - off] : 0;
        __syncthreads(); sh[tid] += t; __syncthreads();
    }
    if (tid < NB1) g_bsums[tid] = sh[tid] - v;
}

__global__ void k_scan3() {
    int i = blockIdx.x * 256 + threadIdx.x;
    if (i < NNODES) {
        int r = g_row[i] + g_bsums[blockIdx.x];
        g_row[i] = r;
        g_cursor[i] = r;
        if (i == 0) g_row[NNODES] = NEDGES;
    }
}

__global__ void k_sort(const void* __restrict__ ei, const float* __restrict__ ew) {
    int e = blockIdx.x * 256 + threadIdx.x;
    if (e < NEDGES) {
        int s, d;
        load_edge(ei, e, s, d);
        float nrm = g_dis[s] * ew[e] * g_dis[d];
        int pos = atomicAdd(&g_cursor[d], 1);
        g_edge[pos] = make_int2(s, __float_as_int(nrm));
    }
}

// ---------------- GEMM via packed f32x2: (M x 128) @ (128 x NCOL) ----------
// (exact round-5 winner: float k-major Xs, inline dup2 for B, acc[4][TC])
template<int NCOL, int LAYER>
__global__ __launch_bounds__(256, 2) void gemm(
    const float* __restrict__ Xin, const float* __restrict__ W, int M)
{
    constexpr int TC = NCOL / 16;    // cols per thread (8 or 4)
    constexpr int BK = 32;
    constexpr int XSS = 132;         // padded stride (16B-aligned, low conflict)
    __shared__ __align__(16) float Xs[BK * XSS];
    __shared__ __align__(16) float Ws[BK * NCOL];

    const float* __restrict__ X = (LAYER == 1) ? Xin : g_a1;
    float* __restrict__ H = (LAYER == 1) ? g_h1 : g_h2;

    const int tid  = threadIdx.x;
    const int row0 = blockIdx.x * 128;
    const int tc   = tid & 15;
    const int tr   = tid >> 4;

    ull acc[4][TC];
#pragma unroll
    for (int p = 0; p < 4; p++)
#pragma unroll
        for (int j = 0; j < TC; j++) acc[p][j] = 0ull;

    for (int kt = 0; kt < 128 / BK; kt++) {
        // X tile (transpose into k-major smem)
#pragma unroll
        for (int idx = tid; idx < 128 * BK / 4; idx += 256) {
            int r = idx >> 3, c4 = idx & 7;
            float4 v = make_float4(0.f, 0.f, 0.f, 0.f);
            int gr = row0 + r;
            if (gr < M)
                v = reinterpret_cast<const float4*>(X)[(size_t)gr * 32 + kt * 8 + c4];
            int kk = c4 * 4;
            Xs[(kk + 0) * XSS + r] = v.x;
            Xs[(kk + 1) * XSS + r] = v.y;
            Xs[(kk + 2) * XSS + r] = v.z;
            Xs[(kk + 3) * XSS + r] = v.w;
        }
        // W tile (contiguous rows kt*BK .. +BK)
#pragma unroll
        for (int idx = tid; idx < BK * NCOL / 4; idx += 256)
            reinterpret_cast<float4*>(Ws)[idx] =
                reinterpret_cast<const float4*>(W)[kt * (BK * NCOL / 4) + idx];
        __syncthreads();

#pragma unroll
        for (int kk = 0; kk < BK; kk++) {
            ulonglong2 la0 = *reinterpret_cast<const ulonglong2*>(&Xs[kk * XSS + tr * 8]);
            ulonglong2 la1 = *reinterpret_cast<const ulonglong2*>(&Xs[kk * XSS + tr * 8 + 4]);
            ull a[4] = { la0.x, la0.y, la1.x, la1.y };
            ull bb[TC];
            float4 bv0 = *reinterpret_cast<const float4*>(&Ws[kk * NCOL + tc * TC]);
            bb[0] = dup2(bv0.x); bb[1] = dup2(bv0.y);
            bb[2] = dup2(bv0.z); bb[3] = dup2(bv0.w);
            if (TC == 8) {
                float4 bv1 = *reinterpret_cast<const float4*>(&Ws[kk * NCOL + tc * TC + 4]);
                bb[4] = dup2(bv1.x); bb[5] = dup2(bv1.y);
                bb[6] = dup2(bv1.z); bb[7] = dup2(bv1.w);
            }
#pragma unroll
            for (int p = 0; p < 4; p++)
#pragma unroll
                for (int j = 0; j < TC; j++)
                    acc[p][j] = fma2(a[p], bb[j], acc[p][j]);
        }
        __syncthreads();
    }

    // epilogue: acc[p][j] = (row tr*8+2p, row tr*8+2p+1) at col tc*TC+j
#pragma unroll
    for (int p = 0; p < 4; p++) {
        int r0 = row0 + tr * 8 + 2 * p;
#pragma unroll
        for (int j = 0; j < TC; j += 4) {
            float4 v0 = make_float4(lo32(acc[p][j]),     lo32(acc[p][j + 1]),
                                    lo32(acc[p][j + 2]), lo32(acc[p][j + 3]));
            float4 v1 = make_float4(hi32(acc[p][j]),     hi32(acc[p][j + 1]),
                                    hi32(acc[p][j + 2]), hi32(acc[p][j + 3]));
            if (r0 < M)
                reinterpret_cast<float4*>(H)[((size_t)r0 * NCOL + tc * TC + j) >> 2] = v0;
            if (r0 + 1 < M)
                reinterpret_cast<float4*>(H)[((size_t)(r0 + 1) * NCOL + tc * TC + j) >> 2] = v1;
        }
    }
}

// ---------------- segmented aggregation: one warp per dst node --------------
// a1[d] = relu( b1 + dis[d]^2*h1[d] + sum_e norm_e * h1[src_e] ),  C=128
__global__ __launch_bounds__(256) void agg1(const float* __restrict__ bias) {
    int w = (blockIdx.x * 256 + threadIdx.x) >> 5;
    int lane = threadIdx.x & 31;
    if (w >= NNODES) return;
    const ulonglong2* H = reinterpret_cast<const ulonglong2*>(g_h1);

    int beg = g_row[w], end = g_row[w + 1];
    float ds = g_dis[w];
    ull s2 = dup2(ds * ds);
    ulonglong2 hself = H[(size_t)w * 32 + lane];
    ull acc0 = fma2(s2, hself.x, 0ull);
    ull acc1 = fma2(s2, hself.y, 0ull);

    for (int e = beg; e < end; e++) {
        int2 md = g_edge[e];
        ull nm = dup2(__int_as_float(md.y));
        ulonglong2 hv = H[(size_t)md.x * 32 + lane];
        acc0 = fma2(nm, hv.x, acc0);
        acc1 = fma2(nm, hv.y, acc1);
    }
    float4 bv = reinterpret_cast<const float4*>(bias)[lane];
    float4 o;
    o.x = fmaxf(lo32(acc0) + bv.x, 0.f);
    o.y = fmaxf(hi32(acc0) + bv.y, 0.f);
    o.z = fmaxf(lo32(acc1) + bv.z, 0.f);
    o.w = fmaxf(hi32(acc1) + bv.w, 0.f);
    reinterpret_cast<float4*>(g_a1)[(size_t)w * 32 + lane] = o;
}

// out[d] = b2 + dis[d]^2*h2[d] + sum_e norm_e * h2[src_e],  C=64
__global__ __launch_bounds__(256) void agg2(const float* __restrict__ bias,
                                            float* __restrict__ out) {
    int w = (blockIdx.x * 256 + threadIdx.x) >> 5;
    int lane = threadIdx.x & 31;
    if (w >= NNODES) return;
    const ull* H = reinterpret_cast<const ull*>(g_h2);   // 32 u64 per row

    int beg = g_row[w], end = g_row[w + 1];
    float ds = g_dis[w];
    ull s2 = dup2(ds * ds);
    ull acc = fma2(s2, H[(size_t)w * 32 + lane], 0ull);

    for (int e = beg; e < end; e++) {
        int2 md = g_edge[e];
        ull nm = dup2(__int_as_float(md.y));
        acc = fma2(nm, H[(size_t)md.x * 32 + lane], acc);
    }
    float2 bv = reinterpret_cast<const float2*>(bias)[lane];
    float2 o;
    o.x = lo32(acc) + bv.x;
    o.y = hi32(acc) + bv.y;
    reinterpret_cast<float2*>(out)[(size_t)w * 32 + lane] = o;
}

// ---------------- launch ----------------
extern "C" void kernel_launch(void* const* d_in, const int* in_sizes, int n_in,
                              void* d_out, int out_size)
{
    const float* x  = (const float*)d_in[0];
    const void*  ei = d_in[1];
    const float* ew = (const float*)d_in[2];
    const float* W1 = (const float*)d_in[3];
    const float* b1 = (const float*)d_in[4];
    const float* W2 = (const float*)d_in[5];
    const float* b2 = (const float*)d_in[6];
    float* out = (float*)d_out;

    const int nb_nodes = (NNODES + 255) / 256;
    const int nb_edges = (NEDGES + 255) / 256;
    const int nb_rows  = (NNODES + 127) / 128;
    const int nb_warps = (NNODES * 32 + 255) / 256;

    // launch order: the profiler samples launch index 3 -> gemm<128,1>
    k_init<<<nb_nodes, 256>>>((const int*)ei);               // 0
    k_deg<<<nb_edges, 256>>>(ei, ew);                        // 1
    k_scan1<<<nb_nodes, 256>>>();                            // 2
    gemm<128, 1><<<nb_rows, 256>>>(x, W1, NNODES);           // 3  <- profiled
    k_scan2<<<1, 512>>>();                                   // 4
    k_scan3<<<nb_nodes, 256>>>();                            // 5
    k_sort<<<nb_edges, 256>>>(ei, ew);                       // 6
    agg1<<<nb_warps, 256>>>(b1);                             // 7
    gemm<64, 2><<<nb_rows, 256>>>(nullptr, W2, NNODES);      // 8
    agg2<<<nb_warps, 256>>>(b2, out);                        // 9
}

// round 9
// speedup vs baseline: 1.2177x; 1.0163x over previous
#include <cuda_runtime.h>
#include <cuda_bf16.h>
#include <cstdint>

#define NNODES 100000
#define NEDGES 1600000
#define NB1 ((NNODES + 255) / 256)

typedef unsigned long long ull;

// ---------------- scratch (device globals; never passed from host) ---------
__device__ int   g_is64;
__device__ float g_deg[NNODES];
__device__ float g_dis[NNODES];
__device__ int   g_hist[NNODES];
__device__ int   g_row[NNODES + 1];
__device__ int   g_cursor[NNODES];
__device__ int   g_bsums[NB1];
__device__ int2  g_edge[NEDGES];
__device__ float g_h1[(size_t)NNODES * 128];
__device__ float g_a1[(size_t)NNODES * 128];
__device__ float g_h2[(size_t)NNODES * 64];

// ---------------- f32x2 helpers (agg kernels) ----------------
__device__ __forceinline__ ull dup2(float v) {
    ull r; asm("mov.b64 %0, {%1,%1};" : "=l"(r) : "r"(__float_as_uint(v))); return r;
}
__device__ __forceinline__ ull fma2(ull a, ull b, ull c) {
    ull d; asm("fma.rn.f32x2 %0, %1, %2, %3;" : "=l"(d) : "l"(a), "l"(b), "l"(c)); return d;
}
__device__ __forceinline__ float lo32(ull v) { return __uint_as_float((unsigned)v); }
__device__ __forceinline__ float hi32(ull v) { return __uint_as_float((unsigned)(v >> 32)); }

// ---------------- mma helpers (portable PTX, no 'a' features) ----------------
__device__ __forceinline__ uint32_t smem_u32(const void* p) {
    uint32_t a;
    asm("{ .reg .u64 t; cvta.to.shared.u64 t, %1; cvt.u32.u64 %0, t; }" : "=r"(a) : "l"(p));
    return a;
}
#define LDSM_X4(r, addr) \
    asm volatile("ldmatrix.sync.aligned.m8n8.x4.shared.b16 {%0,%1,%2,%3}, [%4];" \
        : "=r"((r)[0]), "=r"((r)[1]), "=r"((r)[2]), "=r"((r)[3]) : "r"(addr))
#define LDSM_X2(r, addr) \
    asm volatile("ldmatrix.sync.aligned.m8n8.x2.shared.b16 {%0,%1}, [%2];" \
        : "=r"((r)[0]), "=r"((r)[1]) : "r"(addr))
#define MMA_BF16(c, a, b) \
    asm volatile("mma.sync.aligned.m16n8k16.row.col.f32.bf16.bf16.f32 " \
        "{%0,%1,%2,%3}, {%4,%5,%6,%7}, {%8,%9}, {%0,%1,%2,%3};" \
        : "+f"((c)[0]), "+f"((c)[1]), "+f"((c)[2]), "+f"((c)[3]) \
        : "r"((a)[0]), "r"((a)[1]), "r"((a)[2]), "r"((a)[3]), \
          "r"((b)[0]), "r"((b)[1]))

__device__ __forceinline__ uint32_t pack_bf16x2(float f0, float f1) {
    uint32_t r;
    asm("cvt.rn.satfinite.bf16x2.f32 %0, %1, %2;" : "=r"(r) : "f"(f1), "f"(f0));
    return r;   // low half = bf16(f0), high half = bf16(f1)
}

// ---------------- init (+ fused edge_index dtype detection) ----------------
__global__ void k_init(const int* __restrict__ ei_raw) {
    int i = blockIdx.x * 256 + threadIdx.x;
    if (i < NNODES) { g_deg[i] = 1.0f; g_hist[i] = 0; }
    if (blockIdx.x == 0) {
        int bad = 0;
        for (int k = threadIdx.x; k < 2048; k += 256)
            bad |= (ei_raw[2 * k + 1] != 0);
        bad = __syncthreads_or(bad);
        if (threadIdx.x == 0) g_is64 = !bad;
    }
}

__device__ __forceinline__ void load_edge(const void* __restrict__ ei, int e,
                                          int& s, int& d) {
    if (g_is64) {
        const long long* p = (const long long*)ei;
        s = (int)p[e]; d = (int)p[NEDGES + e];
    } else {
        const int* p = (const int*)ei;
        s = p[e]; d = p[NEDGES + e];
    }
}

__global__ void k_deg(const void* __restrict__ ei, const float* __restrict__ ew) {
    int e = blockIdx.x * 256 + threadIdx.x;
    if (e < NEDGES) {
        int s, d; load_edge(ei, e, s, d);
        atomicAdd(&g_deg[d], ew[e]);
        atomicAdd(&g_hist[d], 1);
    }
}

__global__ void k_scan1() {
    __shared__ int sh[256];
    int i = blockIdx.x * 256 + threadIdx.x;
    int tid = threadIdx.x;
    if (i < NNODES) g_dis[i] = rsqrtf(g_deg[i]);
    int v = (i < NNODES) ? g_hist[i] : 0;
    sh[tid] = v; __syncthreads();
    for (int off = 1; off < 256; off <<= 1) {
        int t = (tid >= off) ? sh[tid - off] : 0;
        __syncthreads(); sh[tid] += t; __syncthreads();
    }
    if (i < NNODES) g_row[i] = sh[tid] - v;
    if (tid == 255) g_bsums[blockIdx.x] = sh[tid];
}

__global__ void k_scan2() {
    __shared__ int sh[512];
    int tid = threadIdx.x;
    int v = (tid < NB1) ? g_bsums[tid] : 0;
    sh[tid] = v; __syncthreads();
    for (int off = 1; off < 512; off <<= 1) {
        int t = (tid >= off) ? sh[tid - off] : 0;
        __syncthreads(); sh[tid] += t; __syncthreads();
    }
    if (tid < NB1) g_bsums[tid] = sh[tid] - v;
}

__global__ void k_scan3() {
    int i = blockIdx.x * 256 + threadIdx.x;
    if (i < NNODES) {
        int r = g_row[i] + g_bsums[blockIdx.x];
        g_row[i] = r;
        g_cursor[i] = r;
        if (i == 0) g_row[NNODES] = NEDGES;
    }
}

__global__ void k_sort(const void* __restrict__ ei, const float* __restrict__ ew) {
    int e = blockIdx.x * 256 + threadIdx.x;
    if (e < NEDGES) {
        int s, d; load_edge(ei, e, s, d);
        float nrm = g_dis[s] * ew[e] * g_dis[d];
        int pos = atomicAdd(&g_cursor[d], 1);
        g_edge[pos] = make_int2(s, __float_as_int(nrm));
    }
}

// ---------------- tensor-core GEMM: H[M,NCOL] = X[M,128] @ W[128,NCOL] -----
// bf16 split precision via mma.sync m16n8k16 (portable HMMA path).
// smem: Xhi/Xlo [128 rows][136 bf16], Wt hi/lo [(n) NCOL rows][136 bf16] (W^T).
// mma B col-major fragment == plain ldmatrix over (n,k) row-major storage.
template<int NCOL, int LAYER>
__global__ __launch_bounds__(256) void gemm_mma(
    const float* __restrict__ Xin, const float* __restrict__ W, int M)
{
    constexpr int STR = 272;                 // bytes per bf16 row (136 bf16)
    constexpr int XT  = 128 * STR;           // 34816 B per X tile
    constexpr int WT  = NCOL * STR;          // W^T tile bytes
    constexpr int NF  = NCOL / 8;            // n-fragments per warp

    extern __shared__ __align__(16) char smem[];
    char* xhi = smem;
    char* xlo = xhi + XT;
    char* whi = xlo + XT;
    char* wlo = whi + WT;

    const float* __restrict__ X = (LAYER == 1) ? Xin : g_a1;
    float* __restrict__ H = (LAYER == 1) ? g_h1 : g_h2;

    const int tid  = threadIdx.x;
    const int lane = tid & 31;
    const int wid  = tid >> 5;
    const int row0 = blockIdx.x * 128;
    const int valid = M - row0;

    // ---- stage X (128 x 128 fp32 -> bf16 hi/lo), row-major stride 136 ----
    for (int u = tid; u < 128 * 64; u += 256) {
        int r = u >> 6, c2 = (u & 63) << 1;
        float f0 = 0.f, f1 = 0.f;
        if (r < valid) {
            float2 v = *reinterpret_cast<const float2*>(X + (size_t)(row0 + r) * 128 + c2);
            f0 = v.x; f1 = v.y;
        }
        uint32_t hp = pack_bf16x2(f0, f1);
        float h0 = __uint_as_float(hp << 16);
        float h1 = __uint_as_float(hp & 0xFFFF0000u);
        uint32_t lp = pack_bf16x2(f0 - h0, f1 - h1);
        *reinterpret_cast<uint32_t*>(xhi + r * STR + c2 * 2) = hp;
        *reinterpret_cast<uint32_t*>(xlo + r * STR + c2 * 2) = lp;
    }
    // ---- stage W^T: Wt[n][k] = W[k][n]; coalesced loads, scattered STS ----
    for (int u = tid; u < 128 * NCOL; u += 256) {
        int k = u / NCOL, n = u % NCOL;      // u == k*NCOL + n
        float f = W[u];
        __nv_bfloat16 hb = __float2bfloat16(f);
        float hf = __bfloat162float(hb);
        __nv_bfloat16 lb = __float2bfloat16(f - hf);
        *reinterpret_cast<__nv_bfloat16*>(whi + n * STR + k * 2) = hb;
        *reinterpret_cast<__nv_bfloat16*>(wlo + n * STR + k * 2) = lb;
    }
    __syncthreads();

    // ---- per-lane ldmatrix base addresses ----
    const int mb = wid * 16;
    int a_row = mb + (lane & 7) + ((lane >> 3) & 1) * 8;
    uint32_t a_off = a_row * STR + ((lane >> 4) & 1) * 16;
    uint32_t ah_base = smem_u32(xhi) + a_off;
    uint32_t al_base = smem_u32(xlo) + a_off;
    uint32_t b_off = (lane & 7) * STR + ((lane >> 3) & 1) * 16;
    uint32_t bh_base = smem_u32(whi) + b_off;
    uint32_t bl_base = smem_u32(wlo) + b_off;

    float c[NF][4];
#pragma unroll
    for (int nf = 0; nf < NF; nf++)
#pragma unroll
        for (int q = 0; q < 4; q++) c[nf][q] = 0.f;

#pragma unroll
    for (int ks = 0; ks < 8; ks++) {
        uint32_t ah[4], al[4];
        LDSM_X4(ah, ah_base + ks * 32);
        LDSM_X4(al, al_base + ks * 32);
#pragma unroll
        for (int nf = 0; nf < NF; nf++) {
            uint32_t bh[2], bl[2];
            LDSM_X2(bh, bh_base + nf * 8 * STR + ks * 32);
            LDSM_X2(bl, bl_base + nf * 8 * STR + ks * 32);
            MMA_BF16(c[nf], ah, bh);   // hi * hi
            MMA_BF16(c[nf], ah, bl);   // hi * lo
            MMA_BF16(c[nf], al, bh);   // lo * hi
        }
    }

    // ---- epilogue: c-frag -> H ----
    int r0 = row0 + mb + (lane >> 2);
    int cb = (lane & 3) * 2;
#pragma unroll
    for (int nf = 0; nf < NF; nf++) {
        if (r0 < M) {
            float2 v = make_float2(c[nf][0], c[nf][1]);
            *reinterpret_cast<float2*>(&H[(size_t)r0 * NCOL + nf * 8 + cb]) = v;
        }
        if (r0 + 8 < M) {
            float2 v = make_float2(c[nf][2], c[nf][3]);
            *reinterpret_cast<float2*>(&H[(size_t)(r0 + 8) * NCOL + nf * 8 + cb]) = v;
        }
    }
}

// ---------------- segmented aggregation (unchanged) ----------------
__global__ __launch_bounds__(256) void agg1(const float* __restrict__ bias) {
    int w = (blockIdx.x * 256 + threadIdx.x) >> 5;
    int lane = threadIdx.x & 31;
    if (w >= NNODES) return;
    const ulonglong2* H = reinterpret_cast<const ulonglong2*>(g_h1);

    int beg = g_row[w], end = g_row[w + 1];
    float ds = g_dis[w];
    ull s2 = dup2(ds * ds);
    ulonglong2 hself = H[(size_t)w * 32 + lane];
    ull acc0 = fma2(s2, hself.x, 0ull);
    ull acc1 = fma2(s2, hself.y, 0ull);

    for (int e = beg; e < end; e++) {
        int2 md = g_edge[e];
        ull nm = dup2(__int_as_float(md.y));
        ulonglong2 hv = H[(size_t)md.x * 32 + lane];
        acc0 = fma2(nm, hv.x, acc0);
        acc1 = fma2(nm, hv.y, acc1);
    }
    float4 bv = reinterpret_cast<const float4*>(bias)[lane];
    float4 o;
    o.x = fmaxf(lo32(acc0) + bv.x, 0.f);
    o.y = fmaxf(hi32(acc0) + bv.y, 0.f);
    o.z = fmaxf(lo32(acc1) + bv.z, 0.f);
    o.w = fmaxf(hi32(acc1) + bv.w, 0.f);
    reinterpret_cast<float4*>(g_a1)[(size_t)w * 32 + lane] = o;
}

__global__ __launch_bounds__(256) void agg2(const float* __restrict__ bias,
                                            float* __restrict__ out) {
    int w = (blockIdx.x * 256 + threadIdx.x) >> 5;
    int lane = threadIdx.x & 31;
    if (w >= NNODES) return;
    const ull* H = reinterpret_cast<const ull*>(g_h2);

    int beg = g_row[w], end = g_row[w + 1];
    float ds = g_dis[w];
    ull s2 = dup2(ds * ds);
    ull acc = fma2(s2, H[(size_t)w * 32 + lane], 0ull);

    for (int e = beg; e < end; e++) {
        int2 md = g_edge[e];
        ull nm = dup2(__int_as_float(md.y));
        acc = fma2(nm, H[(size_t)md.x * 32 + lane], acc);
    }
    float2 bv = reinterpret_cast<const float2*>(bias)[lane];
    float2 o;
    o.x = lo32(acc) + bv.x;
    o.y = hi32(acc) + bv.y;
    reinterpret_cast<float2*>(out)[(size_t)w * 32 + lane] = o;
}

// ---------------- launch ----------------
extern "C" void kernel_launch(void* const* d_in, const int* in_sizes, int n_in,
                              void* d_out, int out_size)
{
    const float* x  = (const float*)d_in[0];
    const void*  ei = d_in[1];
    const float* ew = (const float*)d_in[2];
    const float* W1 = (const float*)d_in[3];
    const float* b1 = (const float*)d_in[4];
    const float* W2 = (const float*)d_in[5];
    const float* b2 = (const float*)d_in[6];
    float* out = (float*)d_out;

    const int nb_nodes = (NNODES + 255) / 256;
    const int nb_edges = (NEDGES + 255) / 256;
    const int nb_rows  = (NNODES + 127) / 128;
    const int nb_warps = (NNODES * 32 + 255) / 256;

    constexpr int SM1 = 2 * (128 * 272) + 2 * (128 * 272);  // 139264 B
    constexpr int SM2 = 2 * (128 * 272) + 2 * (64 * 272);   // 104448 B
    cudaFuncSetAttribute(gemm_mma<128, 1>, cudaFuncAttributeMaxDynamicSharedMemorySize, SM1);
    cudaFuncSetAttribute(gemm_mma<64, 2>,  cudaFuncAttributeMaxDynamicSharedMemorySize, SM2);

    k_init<<<nb_nodes, 256>>>((const int*)ei);                   // 0
    k_deg<<<nb_edges, 256>>>(ei, ew);                            // 1
    k_scan1<<<nb_nodes, 256>>>();                                // 2
    gemm_mma<128, 1><<<nb_rows, 256, SM1>>>(x, W1, NNODES);      // 3  <- profiled
    k_scan2<<<1, 512>>>();                                       // 4
    k_scan3<<<nb_nodes, 256>>>();                                // 5
    k_sort<<<nb_edges, 256>>>(ei, ew);                           // 6
    agg1<<<nb_warps, 256>>>(b1);                                 // 7
    gemm_mma<64, 2><<<nb_rows, 256, SM2>>>(nullptr, W2, NNODES); // 8
    agg2<<<nb_warps, 256>>>(b2, out);                            // 9
}